// round 5
// baseline (speedup 1.0000x reference)
#include <cuda_runtime.h>

#define B_ 8
#define C_ 32
#define F_ 32
#define Q_ 9
#define H_ 32
#define W_ 32

#define PROWS 18
#define PSTR  36
#define PLANEF (PROWS * PSTR)   // 648

typedef unsigned long long u64;

__device__ __forceinline__ u64 pack2(float lo, float hi) {
    u64 r; asm("mov.b64 %0, {%1, %2};" : "=l"(r) : "f"(lo), "f"(hi)); return r;
}
__device__ __forceinline__ void unpack2(u64 v, float& lo, float& hi) {
    asm("mov.b64 {%0, %1}, %2;" : "=f"(lo), "=f"(hi) : "l"(v));
}
__device__ __forceinline__ u64 fma2(u64 a, u64 b, u64 c) {
    u64 d; asm("fma.rn.f32x2 %0, %1, %2, %3;" : "=l"(d) : "l"(a), "l"(b), "l"(c)); return d;
}
__device__ __forceinline__ u64 mul2(u64 a, u64 b) {
    u64 d; asm("mul.rn.f32x2 %0, %1, %2;" : "=l"(d) : "l"(a), "l"(b)); return d;
}
__device__ __forceinline__ u64 add2(u64 a, u64 b) {
    u64 d; asm("add.rn.f32x2 %0, %1, %2;" : "=l"(d) : "l"(a), "l"(b)); return d;
}
__device__ __forceinline__ float rcpf(float x) {
    float r; asm("rcp.approx.ftz.f32 %0, %1;" : "=f"(r) : "f"(x)); return r;
}

// smem: cs2 = 9*32*10 u64 = 23040B; planes = 8*648*4 = 20736B (aliased w/ 16KB reduction)
__global__ __launch_bounds__(256, 4) void kaconv_kernel(
    const float* __restrict__ x,
    const float* __restrict__ nums,
    const float* __restrict__ denoms,
    float* __restrict__ out)
{
    __shared__ __align__(16) u64   cs2[Q_ * C_ * 10];
    __shared__ __align__(16) float planes[8 * PLANEF];
    u64* part = (u64*)planes;

    const int tid  = threadIdx.x;
    const int blk  = blockIdx.x;
    const int half = blk & 1;
    const int bf   = blk >> 1;
    const int f    = bf & (F_ - 1);
    const int b    = bf >> 5;
    const int row0 = half * 16;

    const int warp = tid >> 5;
    const int lane = tid & 31;

    // ---- stage duplicated coefficient pairs for this f (once) ----
    for (int e = tid; e < Q_ * C_; e += 256) {
        const int g = f * Q_ * C_ + e;
        const float2* np2 = (const float2*)(nums + (size_t)g * 6);
        const float2 n0 = __ldg(np2);
        const float2 n1 = __ldg(np2 + 1);
        const float2 n2 = __ldg(np2 + 2);
        const float4 d4 = __ldg((const float4*)(denoms + (size_t)g * 4));
        u64* o = cs2 + e * 10;
        o[0] = pack2(n0.x, n0.x); o[1] = pack2(n0.y, n0.y);
        o[2] = pack2(n1.x, n1.x); o[3] = pack2(n1.y, n1.y);
        o[4] = pack2(n2.x, n2.x); o[5] = pack2(n2.y, n2.y);
        o[6] = pack2(d4.x, d4.x); o[7] = pack2(d4.y, d4.y);
        o[8] = pack2(d4.z, d4.z); o[9] = pack2(d4.w, d4.w);
    }

    const float* xb = x + (size_t)(b * C_) * (H_ * W_);

    const u64 ONE2  = 0x3F8000003F800000ULL;
    const u64 AMASK = 0x7FFFFFFF7FFFFFFFULL;

    u64 acc[8];
    #pragma unroll
    for (int j = 0; j < 8; ++j) acc[j] = 0ULL;

    for (int r = 0; r < 4; ++r) {
        __syncthreads();   // coeffs staged (r=0) / previous round's plane reads done

        // ---- each warp stages its own channel plane: rows row0-1..row0+16, cols -1..32 ----
        {
            const int c = r * 8 + warp;
            const float* xc = xb + c * (H_ * W_);
            float* dst = planes + warp * PLANEF;
            const int gc0 = lane - 1;
            #pragma unroll 3
            for (int rr = 0; rr < PROWS; ++rr) {
                const int gr = row0 - 1 + rr;
                const bool rok = (unsigned)gr < H_;
                float v0 = 0.f;
                if (rok && (unsigned)gc0 < W_) v0 = xc[gr * W_ + gc0];
                dst[rr * PSTR + lane] = v0;
                if (lane < 2) {
                    float v1 = 0.f;
                    const int gc1 = lane + 31;
                    if (rok && gc1 < W_) v1 = xc[gr * W_ + gc1];
                    dst[rr * PSTR + lane + 32] = v1;
                }
            }
        }
        __syncthreads();

        const int c = r * 8 + warp;
        const float* pl = planes + warp * PLANEF + lane;

        #pragma unroll
        for (int q = 0; q < Q_; ++q) {
            const int dy = q / 3;
            const int dx = q - dy * 3;
            // 5x LDS.128 broadcast of duplicated coefficient pairs
            const ulonglong2* cp = (const ulonglong2*)(cs2 + (q * C_ + c) * 10);
            const ulonglong2 p01 = cp[0];
            const ulonglong2 p23 = cp[1];
            const ulonglong2 p45 = cp[2];
            const ulonglong2 d12 = cp[3];
            const ulonglong2 d34 = cp[4];

            const float* pw = pl + dy * PSTR + dx;
            #pragma unroll
            for (int j = 0; j < 8; ++j) {
                const float w_lo = pw[(2 * j)     * PSTR];
                const float w_hi = pw[(2 * j + 1) * PSTR];
                const u64 w2 = pack2(w_lo, w_hi);

                u64 num = fma2(p45.y, w2, p45.x);
                num = fma2(num, w2, p23.y);
                num = fma2(num, w2, p23.x);
                num = fma2(num, w2, p01.y);
                num = fma2(num, w2, p01.x);

                u64 den = fma2(d34.y, w2, d34.x);
                den = fma2(den, w2, d12.y);
                den = fma2(den, w2, d12.x);
                den = mul2(den, w2);
                den &= AMASK;
                den = add2(ONE2, den);

                float dl, dh; unpack2(den, dl, dh);
                const u64 rr2 = pack2(rcpf(dl), rcpf(dh));
                acc[j] = fma2(num, rr2, acc[j]);
            }
        }
    }

    // ---- deterministic cross-warp reduction ----
    __syncthreads();                 // all plane reads done; alias smem
    #pragma unroll
    for (int j = 0; j < 8; ++j)
        part[warp * 256 + j * 32 + lane] = acc[j];
    __syncthreads();

    {
        const int j  = tid >> 5;     // row-pair index 0..7
        const int xx = tid & 31;
        u64 s = part[j * 32 + xx];
        #pragma unroll
        for (int w = 1; w < 8; ++w)
            s = add2(s, part[w * 256 + j * 32 + xx]);
        float lo, hi; unpack2(s, lo, hi);
        float* ob = out + ((size_t)(b * F_ + f)) * (H_ * W_);
        ob[(row0 + 2 * j)     * W_ + xx] = lo;
        ob[(row0 + 2 * j + 1) * W_ + xx] = hi;
    }
}

extern "C" void kernel_launch(void* const* d_in, const int* in_sizes, int n_in,
                              void* d_out, int out_size)
{
    const float* x      = (const float*)d_in[0];
    const float* nums   = (const float*)d_in[1];
    const float* denoms = (const float*)d_in[2];
    float* out          = (float*)d_out;
    (void)in_sizes; (void)n_in; (void)out_size;

    kaconv_kernel<<<B_ * F_ * 2, 256>>>(x, nums, denoms, out);
}

// round 6
// speedup vs baseline: 1.1584x; 1.1584x over previous
#include <cuda_runtime.h>

#define B_ 8
#define C_ 32
#define F_ 32
#define Q_ 9
#define H_ 32
#define W_ 32
#define CH 16                    // channels per CTA (2-way split)

#define PROWS 18
#define PSTR  36
#define PLANEF (PROWS * PSTR)

typedef unsigned long long u64;

__device__ float g_part[2][B_ * F_ * H_ * W_];   // per-c-half partials (8 MB)

__device__ __forceinline__ u64 pack2(float lo, float hi) {
    u64 r; asm("mov.b64 %0, {%1, %2};" : "=l"(r) : "f"(lo), "f"(hi)); return r;
}
__device__ __forceinline__ void unpack2(u64 v, float& lo, float& hi) {
    asm("mov.b64 {%0, %1}, %2;" : "=f"(lo), "=f"(hi) : "l"(v));
}
__device__ __forceinline__ u64 fma2(u64 a, u64 b, u64 c) {
    u64 d; asm("fma.rn.f32x2 %0, %1, %2, %3;" : "=l"(d) : "l"(a), "l"(b), "l"(c)); return d;
}
__device__ __forceinline__ u64 mul2(u64 a, u64 b) {
    u64 d; asm("mul.rn.f32x2 %0, %1, %2;" : "=l"(d) : "l"(a), "l"(b)); return d;
}
__device__ __forceinline__ u64 add2(u64 a, u64 b) {
    u64 d; asm("add.rn.f32x2 %0, %1, %2;" : "=l"(d) : "l"(a), "l"(b)); return d;
}
__device__ __forceinline__ float rcpf(float x) {
    float r; asm("rcp.approx.ftz.f32 %0, %1;" : "=f"(r) : "f"(x)); return r;
}

// smem: cs2 = 9*16*10 u64 = 11520B; planes = 2*648*4 = 5184B  -> ~16.8KB
__global__ __launch_bounds__(128, 8) void kaconv_main(
    const float* __restrict__ x,
    const float* __restrict__ nums,
    const float* __restrict__ denoms)
{
    __shared__ __align__(16) u64   cs2[Q_ * CH * 10];
    __shared__ __align__(16) float planes[2][PLANEF];

    const int tid   = threadIdx.x;
    const int blk   = blockIdx.x;
    const int half  = blk & 1;            // row half: 16-row slab
    const int chalf = (blk >> 1) & 1;     // channel half
    const int f     = (blk >> 2) & (F_ - 1);
    const int b     = blk >> 7;
    const int row0  = half * 16;
    const int c0    = chalf * CH;

    // ---- stage duplicated coefficient pairs for (f, c-half) ----
    for (int e = tid; e < Q_ * CH; e += 128) {
        const int q = e >> 4;
        const int c = e & 15;
        const int g = (f * Q_ + q) * C_ + c0 + c;
        const float2* np2 = (const float2*)(nums + (size_t)g * 6);
        const float2 n0 = __ldg(np2);
        const float2 n1 = __ldg(np2 + 1);
        const float2 n2 = __ldg(np2 + 2);
        const float4 d4 = __ldg((const float4*)(denoms + (size_t)g * 4));
        u64* o = cs2 + e * 10;
        o[0] = pack2(n0.x, n0.x); o[1] = pack2(n0.y, n0.y);
        o[2] = pack2(n1.x, n1.x); o[3] = pack2(n1.y, n1.y);
        o[4] = pack2(n2.x, n2.x); o[5] = pack2(n2.y, n2.y);
        o[6] = pack2(d4.x, d4.x); o[7] = pack2(d4.y, d4.y);
        o[8] = pack2(d4.z, d4.z); o[9] = pack2(d4.w, d4.w);
    }

    const float* xb = x + (size_t)(b * C_ + c0) * (H_ * W_);
    const int lane_r = tid >> 5;          // 0..3
    const int col    = tid & 31;

    // stage zero-padded plane: rows row0-1..row0+16, cols -1..32 (no div/mod)
    auto stage = [&](int c, int buf) {
        const float* xc = xb + c * (H_ * W_);
        float* dst = planes[buf];
        const int gc0 = col - 1;
        const bool c0ok = (unsigned)gc0 < W_;
        for (int rr = lane_r; rr < PROWS; rr += 4) {
            const int gr = row0 - 1 + rr;
            const bool rok = (unsigned)gr < H_;
            float v0 = 0.f;
            if (rok & c0ok) v0 = xc[gr * W_ + gc0];
            dst[rr * PSTR + col] = v0;
            if (col < 2) {
                float v1 = 0.f;
                if (rok && col == 0) v1 = xc[gr * W_ + 31];
                dst[rr * PSTR + col + 32] = v1;
            }
        }
    };
    stage(0, 0);

    const u64 ONE2  = 0x3F8000003F800000ULL;
    const u64 AMASK = 0x7FFFFFFF7FFFFFFFULL;

    u64 acc0 = 0ULL, acc1 = 0ULL;

    for (int c = 0; c < CH; ++c) {
        __syncthreads();
        if (c + 1 < CH) stage(c + 1, (c + 1) & 1);
        const float* pl = planes[c & 1] + col;

        #pragma unroll
        for (int q = 0; q < Q_; ++q) {
            const int dy = q / 3;
            const int dx = q - dy * 3;
            const ulonglong2* cp = (const ulonglong2*)(cs2 + (q * CH + c) * 10);
            const ulonglong2 p01 = cp[0];
            const ulonglong2 p23 = cp[1];
            const ulonglong2 p45 = cp[2];
            const ulonglong2 d12 = cp[3];
            const ulonglong2 d34 = cp[4];

            const float* pw = pl + (lane_r + dy) * PSTR + dx;
            const u64 w0 = pack2(pw[0],          pw[4 * PSTR]);
            const u64 w1 = pack2(pw[8 * PSTR],   pw[12 * PSTR]);

            u64 n0 = fma2(p45.y, w0, p45.x);
            n0 = fma2(n0, w0, p23.y);
            n0 = fma2(n0, w0, p23.x);
            n0 = fma2(n0, w0, p01.y);
            n0 = fma2(n0, w0, p01.x);
            u64 e0 = fma2(d34.y, w0, d34.x);
            e0 = fma2(e0, w0, d12.y);
            e0 = fma2(e0, w0, d12.x);
            e0 = mul2(e0, w0);
            e0 &= AMASK;
            e0 = add2(ONE2, e0);
            float el0, eh0; unpack2(e0, el0, eh0);
            acc0 = fma2(n0, pack2(rcpf(el0), rcpf(eh0)), acc0);

            u64 n1 = fma2(p45.y, w1, p45.x);
            n1 = fma2(n1, w1, p23.y);
            n1 = fma2(n1, w1, p23.x);
            n1 = fma2(n1, w1, p01.y);
            n1 = fma2(n1, w1, p01.x);
            u64 e1 = fma2(d34.y, w1, d34.x);
            e1 = fma2(e1, w1, d12.y);
            e1 = fma2(e1, w1, d12.x);
            e1 = mul2(e1, w1);
            e1 &= AMASK;
            e1 = add2(ONE2, e1);
            float el1, eh1; unpack2(e1, el1, eh1);
            acc1 = fma2(n1, pack2(rcpf(el1), rcpf(eh1)), acc1);
        }
    }

    // ---- write 4 partial pixels ----
    float o0, o1, o2, o3;
    unpack2(acc0, o0, o1);
    unpack2(acc1, o2, o3);
    float* pb = g_part[chalf] + ((size_t)(b * F_ + f)) * (H_ * W_);
    pb[(row0 + lane_r)      * W_ + col] = o0;
    pb[(row0 + lane_r + 4)  * W_ + col] = o1;
    pb[(row0 + lane_r + 8)  * W_ + col] = o2;
    pb[(row0 + lane_r + 12) * W_ + col] = o3;
}

__global__ __launch_bounds__(256) void kaconv_reduce(float* __restrict__ out)
{
    const int i = blockIdx.x * 256 + threadIdx.x;   // float4 index
    const float4* p0 = (const float4*)g_part[0];
    const float4* p1 = (const float4*)g_part[1];
    float4 a = p0[i];
    float4 bq = p1[i];
    float4 r;
    r.x = a.x + bq.x; r.y = a.y + bq.y; r.z = a.z + bq.z; r.w = a.w + bq.w;
    ((float4*)out)[i] = r;
}

extern "C" void kernel_launch(void* const* d_in, const int* in_sizes, int n_in,
                              void* d_out, int out_size)
{
    const float* x      = (const float*)d_in[0];
    const float* nums   = (const float*)d_in[1];
    const float* denoms = (const float*)d_in[2];
    float* out          = (float*)d_out;
    (void)in_sizes; (void)n_in; (void)out_size;

    kaconv_main<<<B_ * F_ * 4, 128>>>(x, nums, denoms);
    // 1M floats = 256K float4 -> 1024 blocks x 256 threads
    kaconv_reduce<<<(B_ * F_ * H_ * W_) / (256 * 4), 256>>>(out);
}

// round 7
// speedup vs baseline: 1.2733x; 1.0992x over previous
#include <cuda_runtime.h>

#define B_ 8
#define C_ 32
#define F_ 32
#define Q_ 9
#define H_ 32
#define W_ 32
#define CH 8                     // channels per CTA (4-way split)

#define PROWS 18
#define PSTR  36
#define PLANEF (PROWS * PSTR)

typedef unsigned long long u64;

__device__ float g_part[4][B_ * F_ * H_ * W_];   // per-c-quarter partials (16 MB)

__device__ __forceinline__ u64 pack2(float lo, float hi) {
    u64 r; asm("mov.b64 %0, {%1, %2};" : "=l"(r) : "f"(lo), "f"(hi)); return r;
}
__device__ __forceinline__ void unpack2(u64 v, float& lo, float& hi) {
    asm("mov.b64 {%0, %1}, %2;" : "=f"(lo), "=f"(hi) : "l"(v));
}
__device__ __forceinline__ u64 fma2(u64 a, u64 b, u64 c) {
    u64 d; asm("fma.rn.f32x2 %0, %1, %2, %3;" : "=l"(d) : "l"(a), "l"(b), "l"(c)); return d;
}
__device__ __forceinline__ u64 mul2(u64 a, u64 b) {
    u64 d; asm("mul.rn.f32x2 %0, %1, %2;" : "=l"(d) : "l"(a), "l"(b)); return d;
}
__device__ __forceinline__ u64 add2(u64 a, u64 b) {
    u64 d; asm("add.rn.f32x2 %0, %1, %2;" : "=l"(d) : "l"(a), "l"(b)); return d;
}
__device__ __forceinline__ float rcpf(float x) {
    float r; asm("rcp.approx.ftz.f32 %0, %1;" : "=f"(r) : "f"(x)); return r;
}

// smem: cs2 = 9*8*10 u64 = 5760B; planes = 2*648*4 = 5184B  -> ~10.9KB
__global__ __launch_bounds__(128, 9) void kaconv_main(
    const float* __restrict__ x,
    const float* __restrict__ nums,
    const float* __restrict__ denoms)
{
    __shared__ __align__(16) u64   cs2[Q_ * CH * 10];
    __shared__ __align__(16) float planes[2][PLANEF];

    const int tid  = threadIdx.x;
    const int blk  = blockIdx.x;
    const int half = blk & 1;             // row half: 16-row slab
    const int cq   = (blk >> 1) & 3;      // channel quarter
    const int f    = (blk >> 3) & (F_ - 1);
    const int b    = blk >> 8;
    const int row0 = half * 16;
    const int c0   = cq * CH;

    // ---- stage duplicated coefficient pairs for (f, c-quarter) ----
    for (int e = tid; e < Q_ * CH; e += 128) {
        const int q = e >> 3;
        const int c = e & 7;
        const int g = (f * Q_ + q) * C_ + c0 + c;
        const float2* np2 = (const float2*)(nums + (size_t)g * 6);
        const float2 n0 = __ldg(np2);
        const float2 n1 = __ldg(np2 + 1);
        const float2 n2 = __ldg(np2 + 2);
        const float4 d4 = __ldg((const float4*)(denoms + (size_t)g * 4));
        u64* o = cs2 + e * 10;
        o[0] = pack2(n0.x, n0.x); o[1] = pack2(n0.y, n0.y);
        o[2] = pack2(n1.x, n1.x); o[3] = pack2(n1.y, n1.y);
        o[4] = pack2(n2.x, n2.x); o[5] = pack2(n2.y, n2.y);
        o[6] = pack2(d4.x, d4.x); o[7] = pack2(d4.y, d4.y);
        o[8] = pack2(d4.z, d4.z); o[9] = pack2(d4.w, d4.w);
    }

    const float* xb = x + (size_t)(b * C_ + c0) * (H_ * W_);
    const int lane_r = tid >> 5;          // 0..3
    const int col    = tid & 31;

    auto stage = [&](int c, int buf) {
        const float* xc = xb + c * (H_ * W_);
        float* dst = planes[buf];
        const int gc0 = col - 1;
        const bool c0ok = (unsigned)gc0 < W_;
        for (int rr = lane_r; rr < PROWS; rr += 4) {
            const int gr = row0 - 1 + rr;
            const bool rok = (unsigned)gr < H_;
            float v0 = 0.f;
            if (rok & c0ok) v0 = xc[gr * W_ + gc0];
            dst[rr * PSTR + col] = v0;
            if (col < 2) {
                float v1 = 0.f;
                if (rok && col == 0) v1 = xc[gr * W_ + 31];
                dst[rr * PSTR + col + 32] = v1;
            }
        }
    };
    stage(0, 0);

    const u64 ONE2  = 0x3F8000003F800000ULL;
    const u64 AMASK = 0x7FFFFFFF7FFFFFFFULL;

    u64 acc0 = 0ULL, acc1 = 0ULL;

    for (int c = 0; c < CH; ++c) {
        __syncthreads();
        if (c + 1 < CH) stage(c + 1, (c + 1) & 1);
        const float* pl = planes[c & 1] + col;

        #pragma unroll
        for (int q = 0; q < Q_; ++q) {
            const int dy = q / 3;
            const int dx = q - dy * 3;
            const ulonglong2* cp = (const ulonglong2*)(cs2 + (q * CH + c) * 10);
            const ulonglong2 p01 = cp[0];
            const ulonglong2 p23 = cp[1];
            const ulonglong2 p45 = cp[2];
            const ulonglong2 d12 = cp[3];
            const ulonglong2 d34 = cp[4];

            const float* pw = pl + (lane_r + dy) * PSTR + dx;
            const u64 w0 = pack2(pw[0],          pw[4 * PSTR]);
            const u64 w1 = pack2(pw[8 * PSTR],   pw[12 * PSTR]);

            u64 n0 = fma2(p45.y, w0, p45.x);
            n0 = fma2(n0, w0, p23.y);
            n0 = fma2(n0, w0, p23.x);
            n0 = fma2(n0, w0, p01.y);
            n0 = fma2(n0, w0, p01.x);
            u64 e0 = fma2(d34.y, w0, d34.x);
            e0 = fma2(e0, w0, d12.y);
            e0 = fma2(e0, w0, d12.x);
            e0 = mul2(e0, w0);
            e0 &= AMASK;
            e0 = add2(ONE2, e0);
            float el0, eh0; unpack2(e0, el0, eh0);
            acc0 = fma2(n0, pack2(rcpf(el0), rcpf(eh0)), acc0);

            u64 n1 = fma2(p45.y, w1, p45.x);
            n1 = fma2(n1, w1, p23.y);
            n1 = fma2(n1, w1, p23.x);
            n1 = fma2(n1, w1, p01.y);
            n1 = fma2(n1, w1, p01.x);
            u64 e1 = fma2(d34.y, w1, d34.x);
            e1 = fma2(e1, w1, d12.y);
            e1 = fma2(e1, w1, d12.x);
            e1 = mul2(e1, w1);
            e1 &= AMASK;
            e1 = add2(ONE2, e1);
            float el1, eh1; unpack2(e1, el1, eh1);
            acc1 = fma2(n1, pack2(rcpf(el1), rcpf(eh1)), acc1);
        }
    }

    float o0, o1, o2, o3;
    unpack2(acc0, o0, o1);
    unpack2(acc1, o2, o3);
    float* pb = g_part[cq] + ((size_t)(b * F_ + f)) * (H_ * W_);
    pb[(row0 + lane_r)      * W_ + col] = o0;
    pb[(row0 + lane_r + 4)  * W_ + col] = o1;
    pb[(row0 + lane_r + 8)  * W_ + col] = o2;
    pb[(row0 + lane_r + 12) * W_ + col] = o3;
}

__global__ __launch_bounds__(256) void kaconv_reduce(float* __restrict__ out)
{
    const int i = blockIdx.x * 256 + threadIdx.x;   // float4 index
    const float4 a = ((const float4*)g_part[0])[i];
    const float4 bq = ((const float4*)g_part[1])[i];
    const float4 cq = ((const float4*)g_part[2])[i];
    const float4 dq = ((const float4*)g_part[3])[i];
    float4 r;
    r.x = (a.x + bq.x) + (cq.x + dq.x);
    r.y = (a.y + bq.y) + (cq.y + dq.y);
    r.z = (a.z + bq.z) + (cq.z + dq.z);
    r.w = (a.w + bq.w) + (cq.w + dq.w);
    ((float4*)out)[i] = r;
}

extern "C" void kernel_launch(void* const* d_in, const int* in_sizes, int n_in,
                              void* d_out, int out_size)
{
    const float* x      = (const float*)d_in[0];
    const float* nums   = (const float*)d_in[1];
    const float* denoms = (const float*)d_in[2];
    float* out          = (float*)d_out;
    (void)in_sizes; (void)n_in; (void)out_size;

    kaconv_main<<<B_ * F_ * 8, 128>>>(x, nums, denoms);
    kaconv_reduce<<<(B_ * F_ * H_ * W_) / (256 * 4), 256>>>(out);
}

// round 9
// speedup vs baseline: 1.4239x; 1.1183x over previous
#include <cuda_runtime.h>

#define B_ 8
#define C_ 32
#define F_ 32
#define Q_ 9
#define H_ 32
#define W_ 32
#define CH 8

#define PROWS 18
#define PSTR  36
#define PLANEF (PROWS * PSTR)

typedef unsigned long long u64;
typedef unsigned int u32;

__device__ float g_part[4][B_ * F_ * H_ * W_];

__device__ __forceinline__ u64 pack2(float lo, float hi) {
    u64 r; asm("mov.b64 %0, {%1, %2};" : "=l"(r) : "f"(lo), "f"(hi)); return r;
}
__device__ __forceinline__ void unpack2(u64 v, float& lo, float& hi) {
    asm("mov.b64 {%0, %1}, %2;" : "=f"(lo), "=f"(hi) : "l"(v));
}
__device__ __forceinline__ u64 fma2(u64 a, u64 b, u64 c) {
    u64 d; asm("fma.rn.f32x2 %0, %1, %2, %3;" : "=l"(d) : "l"(a), "l"(b), "l"(c)); return d;
}
__device__ __forceinline__ u64 mul2(u64 a, u64 b) {
    u64 d; asm("mul.rn.f32x2 %0, %1, %2;" : "=l"(d) : "l"(a), "l"(b)); return d;
}
__device__ __forceinline__ u64 add2(u64 a, u64 b) {
    u64 d; asm("add.rn.f32x2 %0, %1, %2;" : "=l"(d) : "l"(a), "l"(b)); return d;
}
__device__ __forceinline__ float rcpf(float x) {
    float r; asm("rcp.approx.ftz.f32 %0, %1;" : "=f"(r) : "f"(x)); return r;
}
// cp.async 4B with source-size predication (0 -> zero-fill, no read)
__device__ __forceinline__ void cp4(u32 dst, const float* src, bool ok) {
    const int sz = ok ? 4 : 0;
    asm volatile("cp.async.ca.shared.global [%0], [%1], 4, %2;"
                 :: "r"(dst), "l"(src), "r"(sz));
}

__global__ __launch_bounds__(128, 11) void kaconv_main(
    const float* __restrict__ x,
    const float* __restrict__ nums,
    const float* __restrict__ denoms)
{
    __shared__ __align__(16) u64   cs2[Q_ * CH * 10];
    __shared__ __align__(16) float planes[2][PLANEF];

    const int tid  = threadIdx.x;
    const int blk  = blockIdx.x;
    const int half = blk & 1;
    const int cq   = (blk >> 1) & 3;
    const int f    = (blk >> 3) & (F_ - 1);
    const int b    = blk >> 8;
    const int row0 = half * 16;
    const int c0   = cq * CH;

    // ---- stage duplicated coefficient pairs for (f, c-quarter) ----
    for (int e = tid; e < Q_ * CH; e += 128) {
        const int q = e >> 3;
        const int c = e & 7;
        const int g = (f * Q_ + q) * C_ + c0 + c;
        const float2* np2 = (const float2*)(nums + (size_t)g * 6);
        const float2 n0 = __ldg(np2);
        const float2 n1 = __ldg(np2 + 1);
        const float2 n2 = __ldg(np2 + 2);
        const float4 d4 = __ldg((const float4*)(denoms + (size_t)g * 4));
        u64* o = cs2 + e * 10;
        o[0] = pack2(n0.x, n0.x); o[1] = pack2(n0.y, n0.y);
        o[2] = pack2(n1.x, n1.x); o[3] = pack2(n1.y, n1.y);
        o[4] = pack2(n2.x, n2.x); o[5] = pack2(n2.y, n2.y);
        o[6] = pack2(d4.x, d4.x); o[7] = pack2(d4.y, d4.y);
        o[8] = pack2(d4.z, d4.z); o[9] = pack2(d4.w, d4.w);
    }

    const float* xb = x + (size_t)(b * C_ + c0) * (H_ * W_);
    const int lane_r = tid >> 5;
    const int col    = tid & 31;

    const u32 sm_pl0 = (u32)__cvta_generic_to_shared(planes[0]);
    const u32 sm_pl1 = (u32)__cvta_generic_to_shared(planes[1]);

    // async stage of zero-padded plane: rows row0-1..row0+16, cols -1..32
    auto stage = [&](int c, int buf) {
        const float* xc = xb + c * (H_ * W_);
        const u32 dbase = buf ? sm_pl1 : sm_pl0;
        const int gc0 = col - 1;
        const bool c0ok = (unsigned)gc0 < W_;
        for (int rr = lane_r; rr < PROWS; rr += 4) {
            const int gr = row0 - 1 + rr;
            const bool rok = (unsigned)gr < H_;
            const float* src = xc + (rok ? gr * W_ : 0);
            cp4(dbase + (rr * PSTR + col) * 4, src + (c0ok ? gc0 : 0), rok & c0ok);
            if (col < 2)
                cp4(dbase + (rr * PSTR + col + 32) * 4, src + 31, rok && (col == 0));
        }
        asm volatile("cp.async.commit_group;");
    };
    stage(0, 0);

    const u64 ONE2  = 0x3F8000003F800000ULL;
    const u64 AMASK = 0x7FFFFFFF7FFFFFFFULL;

    u64 acc0 = 0ULL, acc1 = 0ULL;

    for (int c = 0; c < CH; ++c) {
        asm volatile("cp.async.wait_group 0;");
        __syncthreads();
        if (c + 1 < CH) stage(c + 1, (c + 1) & 1);
        const float* pl = planes[c & 1] + col;

        #pragma unroll
        for (int q = 0; q < Q_; ++q) {
            const int dy = q / 3;
            const int dx = q - dy * 3;
            const ulonglong2* cp = (const ulonglong2*)(cs2 + (q * CH + c) * 10);
            const ulonglong2 p01 = cp[0];
            const ulonglong2 p23 = cp[1];
            const ulonglong2 p45 = cp[2];
            const ulonglong2 d12 = cp[3];
            const ulonglong2 d34 = cp[4];

            const float* pw = pl + (lane_r + dy) * PSTR + dx;
            const u64 w0 = pack2(pw[0],          pw[4 * PSTR]);
            const u64 w1 = pack2(pw[8 * PSTR],   pw[12 * PSTR]);

            u64 n0 = fma2(p45.y, w0, p45.x);
            n0 = fma2(n0, w0, p23.y);
            n0 = fma2(n0, w0, p23.x);
            n0 = fma2(n0, w0, p01.y);
            n0 = fma2(n0, w0, p01.x);
            u64 e0 = fma2(d34.y, w0, d34.x);
            e0 = fma2(e0, w0, d12.y);
            e0 = fma2(e0, w0, d12.x);
            e0 = mul2(e0, w0);
            e0 &= AMASK;
            e0 = add2(ONE2, e0);
            float el0, eh0; unpack2(e0, el0, eh0);
            acc0 = fma2(n0, pack2(rcpf(el0), rcpf(eh0)), acc0);

            u64 n1 = fma2(p45.y, w1, p45.x);
            n1 = fma2(n1, w1, p23.y);
            n1 = fma2(n1, w1, p23.x);
            n1 = fma2(n1, w1, p01.y);
            n1 = fma2(n1, w1, p01.x);
            u64 e1 = fma2(d34.y, w1, d34.x);
            e1 = fma2(e1, w1, d12.y);
            e1 = fma2(e1, w1, d12.x);
            e1 = mul2(e1, w1);
            e1 &= AMASK;
            e1 = add2(ONE2, e1);
            float el1, eh1; unpack2(e1, el1, eh1);
            acc1 = fma2(n1, pack2(rcpf(el1), rcpf(eh1)), acc1);
        }
    }

    float o0, o1, o2, o3;
    unpack2(acc0, o0, o1);
    unpack2(acc1, o2, o3);
    float* pb = g_part[cq] + ((size_t)(b * F_ + f)) * (H_ * W_);
    pb[(row0 + lane_r)      * W_ + col] = o0;
    pb[(row0 + lane_r + 4)  * W_ + col] = o1;
    pb[(row0 + lane_r + 8)  * W_ + col] = o2;
    pb[(row0 + lane_r + 12) * W_ + col] = o3;
}

__global__ __launch_bounds__(256) void kaconv_reduce(float* __restrict__ out)
{
    const int i = blockIdx.x * 256 + threadIdx.x;
    const float4 a = ((const float4*)g_part[0])[i];
    const float4 bq = ((const float4*)g_part[1])[i];
    const float4 cq = ((const float4*)g_part[2])[i];
    const float4 dq = ((const float4*)g_part[3])[i];
    float4 r;
    r.x = (a.x + bq.x) + (cq.x + dq.x);
    r.y = (a.y + bq.y) + (cq.y + dq.y);
    r.z = (a.z + bq.z) + (cq.z + dq.z);
    r.w = (a.w + bq.w) + (cq.w + dq.w);
    ((float4*)out)[i] = r;
}

extern "C" void kernel_launch(void* const* d_in, const int* in_sizes, int n_in,
                              void* d_out, int out_size)
{
    const float* x      = (const float*)d_in[0];
    const float* nums   = (const float*)d_in[1];
    const float* denoms = (const float*)d_in[2];
    float* out          = (float*)d_out;
    (void)in_sizes; (void)n_in; (void)out_size;

    kaconv_main<<<B_ * F_ * 8, 128>>>(x, nums, denoms);
    kaconv_reduce<<<(B_ * F_ * H_ * W_) / (256 * 4), 256>>>(out);
}